// round 7
// baseline (speedup 1.0000x reference)
#include <cuda_runtime.h>
#include <math.h>

#define Bn 2048
#define DXc 256
#define DZc 64
#define RX 272          // 258 used, zero-padded
#define RZ 80           // 66 used, zero-padded
#define INV_B (1.0f/2048.0f)
#define NBLK 296        // norm kernel grid (2 blocks/SM on 148 SMs)

// ------------- device scratch (static, no allocations) -------------
__device__ float g_K0 [Bn*(size_t)Bn];
__device__ float g_K0T[Bn*(size_t)Bn];
__device__ float g_Ux[Bn*RX];
__device__ float g_Vx[Bn*RX];
__device__ float g_Uz[Bn*RZ];
__device__ float g_Vz[Bn*RZ];
__device__ float g_Y [Bn*RZ];
__device__ float g_R [Bn*RZ];
__device__ float g_S [RX*RZ];
__device__ float g_u[Bn], g_v[Bn];
__device__ float g_ax[Bn], g_az[Bn];
__device__ float g_cx[Bn], g_cz[Bn];
__device__ float g_rowsqx[Bn], g_rowsqz[Bn];
__device__ float g_p[Bn], g_q[Bn], g_m[Bn];
__device__ float g_vxsum[RX], g_vzsum[RZ];
__device__ double g_sumCx, g_sumCz, g_reg, g_cross;
__device__ float g_sx, g_sz, g_mCx2, g_mCz2;
__device__ int g_barCount, g_barSense;

// ------------- helpers -------------
// linear-tid block reduction over 256 threads (t MUST be the linear thread id)
__device__ __forceinline__ float blockReduce256(float v, float* sh, int t) {
    #pragma unroll
    for (int o = 16; o; o >>= 1) v += __shfl_down_sync(0xffffffffu, v, o);
    if ((t & 31) == 0) sh[t >> 5] = v;
    __syncthreads();
    if (t < 32) {
        v = (t < 8) ? sh[t] : 0.0f;
        #pragma unroll
        for (int o = 4; o; o >>= 1) v += __shfl_down_sync(0xffffffffu, v, o);
    }
    __syncthreads();
    return v;  // valid on linear tid 0
}

// ------------- prologue -------------
__global__ void k_init() {
    int t = blockIdx.x * blockDim.x + threadIdx.x;
    if (t == 0) { g_sumCx = 0.0; g_sumCz = 0.0; g_reg = 0.0; g_cross = 0.0; }
    if (t < Bn) { g_rowsqx[t] = 0.0f; g_rowsqz[t] = 0.0f; }
    if (t < RX) g_vxsum[t] = 0.0f;
    if (t < RZ) g_vzsum[t] = 0.0f;
}

__global__ void k_sqnorm(const float* __restrict__ X, int D, int which) {
    __shared__ float sh[8];
    int i = blockIdx.x;
    float s = 0.0f;
    for (int k = threadIdx.x; k < D; k += 256) { float x = X[i * D + k]; s += x * x; }
    s = blockReduce256(s, sh, threadIdx.x);
    if (threadIdx.x == 0) { if (which == 0) g_ax[i] = s; else g_az[i] = s; }
}

// pairwise-distance statistics (no C stored): sum(C), per-row sum(C^2)
__global__ void k_stats(const float* __restrict__ X, int D, int which) {
    __shared__ float Xa[64][17];
    __shared__ float Xb[64][17];
    __shared__ float rowacc[64];
    __shared__ float sh[8];
    int tx = threadIdx.x, ty = threadIdx.y;
    int t = ty * 16 + tx;
    int i0 = blockIdx.y * 64, j0 = blockIdx.x * 64;
    float acc[4][4];
    #pragma unroll
    for (int r = 0; r < 4; r++)
        #pragma unroll
        for (int c = 0; c < 4; c++) acc[r][c] = 0.0f;

    for (int k0 = 0; k0 < D; k0 += 16) {
        #pragma unroll
        for (int e = 0; e < 4; e++) {
            int idx = t + e * 256;
            int r = idx >> 4, kk = idx & 15;
            Xa[r][kk] = X[(i0 + r) * D + k0 + kk];
            Xb[r][kk] = X[(j0 + r) * D + k0 + kk];
        }
        __syncthreads();
        #pragma unroll
        for (int kk = 0; kk < 16; kk++) {
            float fa[4], fb[4];
            #pragma unroll
            for (int r = 0; r < 4; r++) fa[r] = Xa[ty * 4 + r][kk];
            #pragma unroll
            for (int c = 0; c < 4; c++) fb[c] = Xb[tx * 4 + c][kk];
            #pragma unroll
            for (int r = 0; r < 4; r++)
                #pragma unroll
                for (int c = 0; c < 4; c++) acc[r][c] += fa[r] * fb[c];
        }
        __syncthreads();
    }
    const float* a = (which == 0) ? g_ax : g_az;
    float* rowsq   = (which == 0) ? g_rowsqx : g_rowsqz;
    float ai[4], aj[4];
    #pragma unroll
    for (int r = 0; r < 4; r++) ai[r] = a[i0 + ty * 4 + r];
    #pragma unroll
    for (int c = 0; c < 4; c++) aj[c] = a[j0 + tx * 4 + c];

    if (t < 64) rowacc[t] = 0.0f;
    __syncthreads();

    float lsum = 0.0f;
    float lrow[4] = {0.f, 0.f, 0.f, 0.f};
    #pragma unroll
    for (int r = 0; r < 4; r++)
        #pragma unroll
        for (int c = 0; c < 4; c++) {
            float cv = fmaxf(ai[r] + aj[c] - 2.0f * acc[r][c], 0.0f);
            lsum += cv;
            lrow[r] += cv * cv;
        }
    #pragma unroll
    for (int r = 0; r < 4; r++) atomicAdd(&rowacc[ty * 4 + r], lrow[r]);

    float bs = blockReduce256(lsum, sh, t);
    if (t == 0) atomicAdd((which == 0) ? &g_sumCx : &g_sumCz, (double)bs);
    __syncthreads();
    if (t < 64) atomicAdd(&rowsq[i0 + t], rowacc[t]);
}

__global__ void k_scalars() {
    __shared__ float shx[256], shz[256];
    int t = threadIdx.x;
    float s1 = 0.0f, s2 = 0.0f;
    for (int i = t; i < Bn; i += 256) { s1 += g_rowsqx[i]; s2 += g_rowsqz[i]; }
    shx[t] = s1; shz[t] = s2;
    __syncthreads();
    for (int o = 128; o; o >>= 1) {
        if (t < o) { shx[t] += shx[t + o]; shz[t] += shz[t + o]; }
        __syncthreads();
    }
    if (t == 0) {
        float mx = (float)(g_sumCx / ((double)Bn * (double)Bn));
        float mz = (float)(g_sumCz / ((double)Bn * (double)Bn));
        float sx = 1.0f / (mx + 1e-8f);
        float sz = 1.0f / (mz + 1e-8f);
        g_sx = sx; g_sz = sz;
        g_mCx2 = sx * sx * shx[0] / ((float)Bn * (float)Bn);
        g_mCz2 = sz * sz * shz[0] / ((float)Bn * (float)Bn);
    }
}

__global__ void k_buildx(const float* __restrict__ X) {
    int i = blockIdx.x;
    int t = threadIdx.x;          // 0..271
    float sx = g_sx;
    if (t == 0) g_cx[i] = sx * sx * g_rowsqx[i] * INV_B;
    float uv = 0.0f, vv = 0.0f;
    if (t == 0)       { uv = sx * g_ax[i]; vv = 1.0f; }
    else if (t == 1)  { uv = sx;           vv = g_ax[i]; }
    else if (t < 258) { float xv = X[i * DXc + (t - 2)]; uv = sx * xv; vv = -2.0f * xv; }
    g_Ux[i * RX + t] = uv;
    g_Vx[i * RX + t] = vv;
}

__global__ void k_buildz(const float* __restrict__ Z) {
    int i = blockIdx.x;
    int t = threadIdx.x;          // 0..79
    float sz = g_sz;
    if (t == 0) g_cz[i] = sz * sz * g_rowsqz[i] * INV_B;
    float uv = 0.0f, vv = 0.0f;
    if (t == 0)      { uv = sz * g_az[i]; vv = 1.0f; }
    else if (t == 1) { uv = sz;           vv = g_az[i]; }
    else if (t < 66) { float zv = Z[i * DZc + (t - 2)]; uv = sz * zv; vv = -2.0f * zv; }
    g_Uz[i * RZ + t] = uv;
    g_Vz[i * RZ + t] = vv;
}

// column sums of Vx / Vz (coalesced: thread t owns column c, scans rows)
__global__ void k_vsum() {
    int t = threadIdx.x;
    int r0 = blockIdx.x * 128;
    for (int cb = 0; cb < RX; cb += 256) {
        int c = cb + t;
        if (c < RX) {
            float s = 0.0f;
            for (int r = 0; r < 128; r++) s += g_Vx[(r0 + r) * RX + c];
            atomicAdd(&g_vxsum[c], s);
        }
    }
    if (t < RZ) {
        float s = 0.0f;
        for (int r = 0; r < 128; r++) s += g_Vz[(r0 + r) * RZ + t];
        atomicAdd(&g_vzsum[t], s);
    }
}

// p_i = rowsum(Cx)_i = Ux_i . vxsum ; q_i = rowsum(Cz)_i = Uz_i . vzsum
__global__ void k_pq() {
    int i = blockIdx.x * blockDim.x + threadIdx.x;
    if (i >= Bn) return;
    float p = 0.0f;
    for (int k = 0; k < RX; k++) p += g_Ux[i * RX + k] * g_vxsum[k];
    g_p[i] = p;
    float q = 0.0f;
    for (int k = 0; k < RZ; k++) q += g_Uz[i * RZ + k] * g_vzsum[k];
    g_q[i] = q;
}

// iter-1 rowmax: m_i = max_j (2*inv_b*p_i*q_j - cz_j)  (expo row offset; cx_i added in k_K1)
__global__ void k_m1() {
    __shared__ float qs[Bn];
    __shared__ float czs[Bn];
    int t = threadIdx.x;
    for (int j = t; j < Bn; j += 256) { qs[j] = g_q[j]; czs[j] = g_cz[j]; }
    __syncthreads();
    int i = blockIdx.x * 256 + t;
    float pi2 = 2.0f * INV_B * g_p[i];
    float m = -1e30f;
    for (int j = 0; j < Bn; j++) m = fmaxf(m, pi2 * qs[j] - czs[j]);
    g_m[i] = m;
}

// iter-1 K build (rank-1 exponent, stabilized): K0 = exp(2*inv_b*p_i*q_j - cx_i - cz_j - m_i)
__global__ void k_K1() {
    int tx = threadIdx.x, ty = threadIdx.y;
    int i0 = blockIdx.y * 64, j0 = blockIdx.x * 64;
    float pr[4], qc[4], czc[4];
    #pragma unroll
    for (int r = 0; r < 4; r++) {
        int i = i0 + ty * 4 + r;
        pr[r] = 2.0f * INV_B * g_p[i];
    }
    float off[4];
    #pragma unroll
    for (int r = 0; r < 4; r++) {
        int i = i0 + ty * 4 + r;
        off[r] = g_cx[i] + g_m[i];
    }
    #pragma unroll
    for (int c = 0; c < 4; c++) {
        int j = j0 + tx * 4 + c;
        qc[c] = g_q[j];
        czc[c] = g_cz[j];
    }
    float val[4][4];
    #pragma unroll
    for (int r = 0; r < 4; r++)
        #pragma unroll
        for (int c = 0; c < 4; c++)
            val[r][c] = __expf(pr[r] * qc[c] - czc[c] - off[r]);
    #pragma unroll
    for (int r = 0; r < 4; r++) {
        float4 w = make_float4(val[r][0], val[r][1], val[r][2], val[r][3]);
        *(float4*)&g_K0[(size_t)(i0 + ty * 4 + r) * Bn + j0 + tx * 4] = w;
    }
    #pragma unroll
    for (int c = 0; c < 4; c++) {
        float4 w = make_float4(val[0][c], val[1][c], val[2][c], val[3][c]);
        *(float4*)&g_K0T[(size_t)(j0 + tx * 4 + c) * Bn + i0 + ty * 4] = w;
    }
}

// regularizer: computed on the fly from z (C_z never materialized)
__global__ void k_reg(const float* __restrict__ Z, const float* __restrict__ y) {
    __shared__ float zi[16][65];
    __shared__ float zj[128][65];
    __shared__ float yis[16], azis[16];
    __shared__ float sh[8];
    int t = threadIdx.x;
    int i0 = blockIdx.x * 16;
    float sz = g_sz;
    for (int idx = t; idx < 16 * 64; idx += 256) {
        int r = idx >> 6, k = idx & 63;
        zi[r][k] = Z[(i0 + r) * DZc + k];
    }
    if (t < 16) { yis[t] = y[i0 + t]; azis[t] = g_az[i0 + t]; }
    __syncthreads();

    int half = t >> 7;
    int jl = t & 127;
    float acc = 0.0f;
    for (int j0 = 0; j0 < Bn; j0 += 128) {
        __syncthreads();
        for (int idx = t; idx < 128 * 64; idx += 256) {
            int r = idx >> 6, k = idx & 63;
            zj[r][k] = Z[(j0 + r) * DZc + k];
        }
        __syncthreads();
        int j = j0 + jl;
        float azj = g_az[j];
        float yj = y[j];
        #pragma unroll
        for (int ii = 0; ii < 8; ii++) {
            int il = half * 8 + ii;
            int i = i0 + il;
            if (i == j) continue;
            float d = 0.0f;
            #pragma unroll 16
            for (int k = 0; k < 64; k++) d += zi[il][k] * zj[jl][k];
            float raw = azis[il] + azj - 2.0f * d;
            float Cz = sz * fmaxf(raw, 0.0f);
            float zd = fmaxf(Cz, 1e-4f);
            float df = __logf(fabsf(yis[il] - yj) + 1e-6f) - __logf(zd + 1e-6f);
            acc += df * df;
        }
    }
    float bs = blockReduce256(acc, sh, t);
    if (t == 0) atomicAdd(&g_reg, (double)bs);
}

// ------------- loop kernels -------------
// Y[i,c] = u_i * sum_j K0[i,j] * v_j * Vz[j,c]
__global__ void k_gemm1() {
    __shared__ float Ks[64][17];
    __shared__ float Vs[16][16];
    int tx = threadIdx.x, ty = threadIdx.y;
    int t = ty * 16 + tx;
    int i0 = blockIdx.x * 64, c0 = blockIdx.y * 16;
    float acc[4] = {0.f, 0.f, 0.f, 0.f};
    for (int j0 = 0; j0 < Bn; j0 += 16) {
        #pragma unroll
        for (int e = 0; e < 4; e++) {
            int idx = t + e * 256;
            int r = idx >> 4, kk = idx & 15;
            Ks[r][kk] = g_K0[(size_t)(i0 + r) * Bn + j0 + kk];
        }
        Vs[ty][tx] = g_v[j0 + ty] * g_Vz[(j0 + ty) * RZ + c0 + tx];
        __syncthreads();
        #pragma unroll
        for (int jj = 0; jj < 16; jj++) {
            float b = Vs[jj][tx];
            #pragma unroll
            for (int r = 0; r < 4; r++) acc[r] += Ks[ty * 4 + r][jj] * b;
        }
        __syncthreads();
    }
    #pragma unroll
    for (int r = 0; r < 4; r++) {
        int i = i0 + ty * 4 + r;
        g_Y[i * RZ + c0 + tx] = g_u[i] * acc[r];
    }
}

// S[k,c] = sum_i Vx[i,k] * Y[i,c]
__global__ void k_gemm2() {
    __shared__ float Vxs[64][17];
    __shared__ float Ys[64][17];
    int tx = threadIdx.x, ty = threadIdx.y;
    int t = ty * 16 + tx;
    int k0 = blockIdx.x * 16, c0 = blockIdx.y * 16;
    float acc = 0.0f;
    for (int i0 = 0; i0 < Bn; i0 += 64) {
        #pragma unroll
        for (int e = 0; e < 4; e++) {
            int idx = t + e * 256;
            int r = idx >> 4, q = idx & 15;
            Vxs[r][q] = g_Vx[(i0 + r) * RX + k0 + q];
            Ys[r][q]  = g_Y[(i0 + r) * RZ + c0 + q];
        }
        __syncthreads();
        #pragma unroll
        for (int ii = 0; ii < 64; ii++) acc += Vxs[ii][ty] * Ys[ii][tx];
        __syncthreads();
    }
    g_S[(k0 + ty) * RZ + c0 + tx] = acc;
}

// R[i,c] = sum_k Ux[i,k] * S[k,c]
__global__ void k_gemm3() {
    __shared__ float Uxs[64][17];
    __shared__ float Ss[16][17];
    int tx = threadIdx.x, ty = threadIdx.y;
    int t = ty * 16 + tx;
    int i0 = blockIdx.x * 64, c0 = blockIdx.y * 16;
    float acc[4] = {0.f, 0.f, 0.f, 0.f};
    for (int k0 = 0; k0 < RX; k0 += 16) {
        #pragma unroll
        for (int e = 0; e < 4; e++) {
            int idx = t + e * 256;
            int r = idx >> 4, q = idx & 15;
            Uxs[r][q] = g_Ux[(i0 + r) * RX + k0 + q];
        }
        Ss[ty][tx] = g_S[(k0 + ty) * RZ + c0 + tx];
        __syncthreads();
        #pragma unroll
        for (int kk = 0; kk < 16; kk++) {
            float b = Ss[kk][tx];
            #pragma unroll
            for (int r = 0; r < 4; r++) acc[r] += Uxs[ty * 4 + r][kk] * b;
        }
        __syncthreads();
    }
    #pragma unroll
    for (int r = 0; r < 4; r++) g_R[(i0 + ty * 4 + r) * RZ + c0 + tx] = acc[r];
}

// K0[i,j] = exp(2 * dot(R_i, Uz_j) - cx_i - cz_j); also write K0T
// (safe unstabilized: for iters >= 2, mass(T) <= 1 so expo <= ~6)
__global__ void k_gemm4() {
    __shared__ float Rs[RZ][68];
    __shared__ float Us[RZ][68];
    int tx = threadIdx.x, ty = threadIdx.y;
    int t = ty * 16 + tx;
    int i0 = blockIdx.y * 64, j0 = blockIdx.x * 64;
    for (int idx = t; idx < 64 * RZ; idx += 256) {
        int row = idx / RZ, k = idx % RZ;
        Rs[k][row] = g_R[(i0 + row) * RZ + k];
        Us[k][row] = g_Uz[(j0 + row) * RZ + k];
    }
    __syncthreads();
    float acc[4][4];
    #pragma unroll
    for (int r = 0; r < 4; r++)
        #pragma unroll
        for (int c = 0; c < 4; c++) acc[r][c] = 0.0f;
    #pragma unroll
    for (int k = 0; k < RZ; k++) {
        float4 fa = *(const float4*)&Rs[k][ty * 4];
        float4 fb = *(const float4*)&Us[k][tx * 4];
        float a4[4] = {fa.x, fa.y, fa.z, fa.w};
        float b4[4] = {fb.x, fb.y, fb.z, fb.w};
        #pragma unroll
        for (int r = 0; r < 4; r++)
            #pragma unroll
            for (int c = 0; c < 4; c++) acc[r][c] += a4[r] * b4[c];
    }
    float cxv[4], czv[4];
    #pragma unroll
    for (int r = 0; r < 4; r++) cxv[r] = g_cx[i0 + ty * 4 + r];
    #pragma unroll
    for (int c = 0; c < 4; c++) czv[c] = g_cz[j0 + tx * 4 + c];
    float val[4][4];
    #pragma unroll
    for (int r = 0; r < 4; r++)
        #pragma unroll
        for (int c = 0; c < 4; c++)
            val[r][c] = __expf(2.0f * acc[r][c] - cxv[r] - czv[c]);
    #pragma unroll
    for (int r = 0; r < 4; r++) {
        float4 w = make_float4(val[r][0], val[r][1], val[r][2], val[r][3]);
        *(float4*)&g_K0[(size_t)(i0 + ty * 4 + r) * Bn + j0 + tx * 4] = w;
    }
    #pragma unroll
    for (int c = 0; c < 4; c++) {
        float4 w = make_float4(val[0][c], val[1][c], val[2][c], val[3][c]);
        *(float4*)&g_K0T[(size_t)(j0 + tx * 4 + c) * Bn + i0 + ty * 4] = w;
    }
}

// fused 5-round normalization with software grid barrier (one launch)
__global__ void __launch_bounds__(256) k_norm() {
    __shared__ float sh[8];
    int tid = threadIdx.x;
    int sense = *((volatile int*)&g_barSense);

    // init u = v = 1 (each iteration builds K fresh)
    {
        int gt = blockIdx.x * 256 + tid;
        if (gt < Bn) { g_u[gt] = 1.0f; g_v[gt] = 1.0f; }
    }

    #define GRID_BAR() do {                                          \
        __syncthreads();                                             \
        __threadfence();                                             \
        if (tid == 0) {                                              \
            int tgt = sense ^ 1;                                     \
            if (atomicAdd(&g_barCount, 1) == NBLK - 1) {             \
                g_barCount = 0;                                      \
                __threadfence();                                     \
                *((volatile int*)&g_barSense) = tgt;                 \
            } else {                                                 \
                while (*((volatile int*)&g_barSense) != tgt) { __nanosleep(32); } \
            }                                                        \
        }                                                            \
        sense ^= 1;                                                  \
        __syncthreads();                                             \
        __threadfence();                                             \
    } while (0)

    GRID_BAR();

    for (int round = 0; round < 5; round++) {
        for (int i = blockIdx.x; i < Bn; i += NBLK) {
            const float* row = &g_K0[(size_t)i * Bn];
            float s = 0.0f;
            #pragma unroll 4
            for (int j = tid; j < Bn; j += 256) s += row[j] * __ldcg(&g_v[j]);
            s = blockReduce256(s, sh, tid);
            if (tid == 0) {
                float uo = g_u[i];
                g_u[i] = uo * INV_B / (uo * s + 1e-8f);
            }
        }
        GRID_BAR();
        for (int j = blockIdx.x; j < Bn; j += NBLK) {
            const float* col = &g_K0T[(size_t)j * Bn];
            float s = 0.0f;
            #pragma unroll 4
            for (int i = tid; i < Bn; i += 256) s += col[i] * __ldcg(&g_u[i]);
            s = blockReduce256(s, sh, tid);
            if (tid == 0) {
                float vo = g_v[j];
                g_v[j] = vo * INV_B / (vo * s + 1e-8f);
            }
        }
        if (round < 4) GRID_BAR();
    }
    #undef GRID_BAR
}

// cross_term = sum_ij dot(R_i,Uz_j) * u_i * K0_ij * v_j
__global__ void k_cross() {
    __shared__ float Rs[RZ][68];
    __shared__ float Us[RZ][68];
    __shared__ float sh[8];
    int tx = threadIdx.x, ty = threadIdx.y;
    int t = ty * 16 + tx;
    int i0 = blockIdx.y * 64, j0 = blockIdx.x * 64;
    for (int idx = t; idx < 64 * RZ; idx += 256) {
        int row = idx / RZ, k = idx % RZ;
        Rs[k][row] = g_R[(i0 + row) * RZ + k];
        Us[k][row] = g_Uz[(j0 + row) * RZ + k];
    }
    __syncthreads();
    float acc[4][4];
    #pragma unroll
    for (int r = 0; r < 4; r++)
        #pragma unroll
        for (int c = 0; c < 4; c++) acc[r][c] = 0.0f;
    #pragma unroll
    for (int k = 0; k < RZ; k++) {
        float4 fa = *(const float4*)&Rs[k][ty * 4];
        float4 fb = *(const float4*)&Us[k][tx * 4];
        float a4[4] = {fa.x, fa.y, fa.z, fa.w};
        float b4[4] = {fb.x, fb.y, fb.z, fb.w};
        #pragma unroll
        for (int r = 0; r < 4; r++)
            #pragma unroll
            for (int c = 0; c < 4; c++) acc[r][c] += a4[r] * b4[c];
    }
    float4 vj = *(const float4*)&g_v[j0 + tx * 4];
    float v4[4] = {vj.x, vj.y, vj.z, vj.w};
    float part = 0.0f;
    #pragma unroll
    for (int r = 0; r < 4; r++) {
        int i = i0 + ty * 4 + r;
        float ui = g_u[i];
        float4 k4 = *(const float4*)&g_K0[(size_t)i * Bn + j0 + tx * 4];
        float kk[4] = {k4.x, k4.y, k4.z, k4.w};
        #pragma unroll
        for (int c = 0; c < 4; c++) part += acc[r][c] * ui * kk[c] * v4[c];
    }
    float bs = blockReduce256(part, sh, t);
    if (t == 0) atomicAdd(&g_cross, (double)bs);
}

__global__ void k_final(float* out) {
    float gw = g_mCx2 + g_mCz2 - 2.0f * (float)g_cross;
    gw = fmaxf(gw, 0.0f);
    double denom = (double)Bn * (double)(Bn - 1);
    out[0] = gw + (float)(g_reg / denom);
}

// ------------- launch -------------
extern "C" void kernel_launch(void* const* d_in, const int* in_sizes, int n_in,
                              void* d_out, int out_size) {
    const float* x = (const float*)d_in[0];
    const float* z = (const float*)d_in[1];
    const float* y = (const float*)d_in[2];
    float* out = (float*)d_out;
    (void)in_sizes; (void)n_in; (void)out_size;

    dim3 t16(16, 16);
    dim3 g3232(32, 32);
    dim3 g1(32, 5);   // gemm1/gemm3: 2048/64 row tiles x 80/16 col tiles
    dim3 g2(17, 5);   // gemm2: 272/16 x 80/16

    k_init<<<8, 256>>>();
    k_sqnorm<<<Bn, 256>>>(x, DXc, 0);
    k_sqnorm<<<Bn, 256>>>(z, DZc, 1);
    k_stats<<<g3232, t16>>>(x, DXc, 0);
    k_stats<<<g3232, t16>>>(z, DZc, 1);
    k_scalars<<<1, 256>>>();
    k_buildx<<<Bn, RX>>>(x);
    k_buildz<<<Bn, RZ>>>(z);
    k_reg<<<Bn / 16, 256>>>(z, y);

    // --- iteration 1: rank-1 exponent, rowmax-stabilized (T0 has mass b => expo ~ +4000) ---
    k_vsum<<<16, 256>>>();
    k_pq<<<8, 256>>>();
    k_m1<<<8, 256>>>();
    k_K1<<<g3232, t16>>>();
    k_norm<<<NBLK, 256>>>();

    // --- iterations 2..50: mass(T) <= 1 so expo is small; no stabilization needed ---
    for (int it = 1; it < 50; it++) {
        k_gemm1<<<g1, t16>>>();
        k_gemm2<<<g2, t16>>>();
        k_gemm3<<<g1, t16>>>();
        k_gemm4<<<g3232, t16>>>();
        k_norm<<<NBLK, 256>>>();
    }
    // final T = diag(u) K0 diag(v); compute cross_term
    k_gemm1<<<g1, t16>>>();
    k_gemm2<<<g2, t16>>>();
    k_gemm3<<<g1, t16>>>();
    k_cross<<<g3232, t16>>>();
    k_final<<<1, 1>>>(out);
}

// round 8
// speedup vs baseline: 1.8513x; 1.8513x over previous
#include <cuda_runtime.h>
#include <math.h>

#define Bn 2048
#define DXc 256
#define DZc 64
#define CQ 80           // padded column count for Y/A/Zb (66 used)
#define INV_B (1.0f/2048.0f)
#define NBLK 296
#define NJ 8            // j-split chunks for phase 1
#define NI 8            // i-split chunks for phase 2

// ------------- device scratch -------------
__device__ float g_K0 [Bn*(size_t)Bn];
__device__ float g_K0T[Bn*(size_t)Bn];
__device__ float g_Zb [Bn*CQ];
__device__ float g_Y  [Bn*CQ];
__device__ float g_Yp [NJ*Bn*CQ];
__device__ float g_P  [DXc*CQ];
__device__ float g_Pp [NI*DXc*CQ];
__device__ float g_csp[NI][CQ], g_asp[NI][CQ];
__device__ float g_cs[CQ], g_asR[CQ];
__device__ float g_A  [Bn*CQ];
__device__ float g_u[Bn], g_v[Bn];
__device__ float g_ax[Bn], g_az[Bn];
__device__ float g_cx[Bn], g_cz[Bn];
__device__ float g_rowsqx[Bn], g_rowsqz[Bn];
__device__ float g_p[Bn], g_q[Bn], g_m[Bn];
__device__ float g_xs[DXc], g_zs[DZc];
__device__ float g_sax, g_saz;
__device__ double g_sumCx, g_sumCz, g_reg, g_cross;
__device__ float g_sx, g_sz, g_mCx2, g_mCz2;
__device__ int g_barCount, g_barSense;

// ------------- helpers -------------
__device__ __forceinline__ float blockReduce256(float v, float* sh, int t) {
    #pragma unroll
    for (int o = 16; o; o >>= 1) v += __shfl_down_sync(0xffffffffu, v, o);
    if ((t & 31) == 0) sh[t >> 5] = v;
    __syncthreads();
    if (t < 32) {
        v = (t < 8) ? sh[t] : 0.0f;
        #pragma unroll
        for (int o = 4; o; o >>= 1) v += __shfl_down_sync(0xffffffffu, v, o);
    }
    __syncthreads();
    return v;
}

// ------------- prologue -------------
__global__ void k_init() {
    int t = blockIdx.x * blockDim.x + threadIdx.x;
    if (t == 0) { g_sumCx = 0.0; g_sumCz = 0.0; g_reg = 0.0; g_cross = 0.0;
                  g_sax = 0.0f; g_saz = 0.0f; }
    if (t < Bn) { g_rowsqx[t] = 0.0f; g_rowsqz[t] = 0.0f; }
    if (t < DXc) g_xs[t] = 0.0f;
    if (t < DZc) g_zs[t] = 0.0f;
}

__global__ void k_sqnorm(const float* __restrict__ X, int D, int which) {
    __shared__ float sh[8];
    int i = blockIdx.x;
    float s = 0.0f;
    for (int k = threadIdx.x; k < D; k += 256) { float x = X[i * D + k]; s += x * x; }
    s = blockReduce256(s, sh, threadIdx.x);
    if (threadIdx.x == 0) { if (which == 0) g_ax[i] = s; else g_az[i] = s; }
}

__global__ void k_stats(const float* __restrict__ X, int D, int which) {
    __shared__ float Xa[64][17];
    __shared__ float Xb[64][17];
    __shared__ float rowacc[64];
    __shared__ float sh[8];
    int tx = threadIdx.x, ty = threadIdx.y;
    int t = ty * 16 + tx;
    int i0 = blockIdx.y * 64, j0 = blockIdx.x * 64;
    float acc[4][4];
    #pragma unroll
    for (int r = 0; r < 4; r++)
        #pragma unroll
        for (int c = 0; c < 4; c++) acc[r][c] = 0.0f;
    for (int k0 = 0; k0 < D; k0 += 16) {
        #pragma unroll
        for (int e = 0; e < 4; e++) {
            int idx = t + e * 256;
            int r = idx >> 4, kk = idx & 15;
            Xa[r][kk] = X[(i0 + r) * D + k0 + kk];
            Xb[r][kk] = X[(j0 + r) * D + k0 + kk];
        }
        __syncthreads();
        #pragma unroll
        for (int kk = 0; kk < 16; kk++) {
            float fa[4], fb[4];
            #pragma unroll
            for (int r = 0; r < 4; r++) fa[r] = Xa[ty * 4 + r][kk];
            #pragma unroll
            for (int c = 0; c < 4; c++) fb[c] = Xb[tx * 4 + c][kk];
            #pragma unroll
            for (int r = 0; r < 4; r++)
                #pragma unroll
                for (int c = 0; c < 4; c++) acc[r][c] += fa[r] * fb[c];
        }
        __syncthreads();
    }
    const float* a = (which == 0) ? g_ax : g_az;
    float* rowsq   = (which == 0) ? g_rowsqx : g_rowsqz;
    float ai[4], aj[4];
    #pragma unroll
    for (int r = 0; r < 4; r++) ai[r] = a[i0 + ty * 4 + r];
    #pragma unroll
    for (int c = 0; c < 4; c++) aj[c] = a[j0 + tx * 4 + c];
    if (t < 64) rowacc[t] = 0.0f;
    __syncthreads();
    float lsum = 0.0f;
    float lrow[4] = {0.f, 0.f, 0.f, 0.f};
    #pragma unroll
    for (int r = 0; r < 4; r++)
        #pragma unroll
        for (int c = 0; c < 4; c++) {
            float cv = fmaxf(ai[r] + aj[c] - 2.0f * acc[r][c], 0.0f);
            lsum += cv;
            lrow[r] += cv * cv;
        }
    #pragma unroll
    for (int r = 0; r < 4; r++) atomicAdd(&rowacc[ty * 4 + r], lrow[r]);
    float bs = blockReduce256(lsum, sh, t);
    if (t == 0) atomicAdd((which == 0) ? &g_sumCx : &g_sumCz, (double)bs);
    __syncthreads();
    if (t < 64) atomicAdd(&rowsq[i0 + t], rowacc[t]);
}

__global__ void k_scalars() {
    __shared__ float shx[256], shz[256];
    int t = threadIdx.x;
    float s1 = 0.0f, s2 = 0.0f;
    for (int i = t; i < Bn; i += 256) { s1 += g_rowsqx[i]; s2 += g_rowsqz[i]; }
    shx[t] = s1; shz[t] = s2;
    __syncthreads();
    for (int o = 128; o; o >>= 1) {
        if (t < o) { shx[t] += shx[t + o]; shz[t] += shz[t + o]; }
        __syncthreads();
    }
    if (t == 0) {
        float mx = (float)(g_sumCx / ((double)Bn * (double)Bn));
        float mz = (float)(g_sumCz / ((double)Bn * (double)Bn));
        float sx = 1.0f / (mx + 1e-8f);
        float sz = 1.0f / (mz + 1e-8f);
        g_sx = sx; g_sz = sz;
        g_mCx2 = sx * sx * shx[0] / ((float)Bn * (float)Bn);
        g_mCz2 = sz * sz * shz[0] / ((float)Bn * (float)Bn);
    }
}

// Zb = [Z | 1 | az | zeros]
__global__ void k_zb(const float* __restrict__ Z) {
    int idx = blockIdx.x * 256 + threadIdx.x;
    if (idx >= Bn * CQ) return;
    int i = idx / CQ, c = idx % CQ;
    float v = 0.0f;
    if (c < 64) v = Z[i * DZc + c];
    else if (c == 64) v = 1.0f;
    else if (c == 65) v = g_az[i];
    g_Zb[idx] = v;
}

// column sums of X, Z and sums of ax, az
__global__ void k_colsums(const float* __restrict__ X, const float* __restrict__ Z) {
    __shared__ float sh[8];
    int t = threadIdx.x;
    int r0 = blockIdx.x * 256;
    float s = 0.0f;
    for (int r = 0; r < 256; r++) s += X[(r0 + r) * DXc + t];
    atomicAdd(&g_xs[t], s);
    if (t < DZc) {
        float s2 = 0.0f;
        for (int r = 0; r < 256; r++) s2 += Z[(r0 + r) * DZc + t];
        atomicAdd(&g_zs[t], s2);
    }
    float a = g_ax[r0 + t];
    float b = g_az[r0 + t];
    float sa = blockReduce256(a, sh, t);
    if (t == 0) atomicAdd(&g_sax, sa);
    float sb = blockReduce256(b, sh, t);
    if (t == 0) atomicAdd(&g_saz, sb);
}

// p_i = rowsum(Cx)_i, q_i = rowsum(Cz)_i; also cx, cz
__global__ void k_pq2(const float* __restrict__ X, const float* __restrict__ Z) {
    int w = threadIdx.x >> 5, lane = threadIdx.x & 31;
    int i = blockIdx.x * 8 + w;
    float s = 0.0f;
    for (int k = lane; k < DXc; k += 32) s += X[i * DXc + k] * g_xs[k];
    #pragma unroll
    for (int o = 16; o; o >>= 1) s += __shfl_down_sync(0xffffffffu, s, o);
    float s2 = 0.0f;
    for (int k = lane; k < DZc; k += 32) s2 += Z[i * DZc + k] * g_zs[k];
    #pragma unroll
    for (int o = 16; o; o >>= 1) s2 += __shfl_down_sync(0xffffffffu, s2, o);
    if (lane == 0) {
        float sx = g_sx, sz = g_sz;
        g_p[i] = sx * ((float)Bn * g_ax[i] + g_sax - 2.0f * s);
        g_q[i] = sz * ((float)Bn * g_az[i] + g_saz - 2.0f * s2);
        g_cx[i] = sx * sx * g_rowsqx[i] * INV_B;
        g_cz[i] = sz * sz * g_rowsqz[i] * INV_B;
    }
}

// iter-1 rowmax
__global__ void k_m1() {
    __shared__ float qs[Bn];
    __shared__ float czs[Bn];
    int t = threadIdx.x;
    for (int j = t; j < Bn; j += 256) { qs[j] = g_q[j]; czs[j] = g_cz[j]; }
    __syncthreads();
    int i = blockIdx.x * 256 + t;
    float pi2 = 2.0f * INV_B * g_p[i];
    float m = -1e30f;
    for (int j = 0; j < Bn; j++) m = fmaxf(m, pi2 * qs[j] - czs[j]);
    g_m[i] = m;
}

// iter-1 K build (rank-1 exponent, stabilized)
__global__ void k_K1() {
    int tx = threadIdx.x, ty = threadIdx.y;
    int i0 = blockIdx.y * 64, j0 = blockIdx.x * 64;
    float pr[4], qc[4], czc[4], off[4];
    #pragma unroll
    for (int r = 0; r < 4; r++) {
        int i = i0 + ty * 4 + r;
        pr[r] = 2.0f * INV_B * g_p[i];
        off[r] = g_cx[i] + g_m[i];
    }
    #pragma unroll
    for (int c = 0; c < 4; c++) {
        int j = j0 + tx * 4 + c;
        qc[c] = g_q[j];
        czc[c] = g_cz[j];
    }
    float val[4][4];
    #pragma unroll
    for (int r = 0; r < 4; r++)
        #pragma unroll
        for (int c = 0; c < 4; c++)
            val[r][c] = __expf(pr[r] * qc[c] - czc[c] - off[r]);
    #pragma unroll
    for (int r = 0; r < 4; r++) {
        float4 w = make_float4(val[r][0], val[r][1], val[r][2], val[r][3]);
        *(float4*)&g_K0[(size_t)(i0 + ty * 4 + r) * Bn + j0 + tx * 4] = w;
    }
    #pragma unroll
    for (int c = 0; c < 4; c++) {
        float4 w = make_float4(val[0][c], val[1][c], val[2][c], val[3][c]);
        *(float4*)&g_K0T[(size_t)(j0 + tx * 4 + c) * Bn + i0 + ty * 4] = w;
    }
}

// regularizer
__global__ void k_reg(const float* __restrict__ Z, const float* __restrict__ y) {
    __shared__ float zi[16][65];
    __shared__ float zj[128][65];
    __shared__ float yis[16], azis[16];
    __shared__ float sh[8];
    int t = threadIdx.x;
    int i0 = blockIdx.x * 16;
    float sz = g_sz;
    for (int idx = t; idx < 16 * 64; idx += 256) {
        int r = idx >> 6, k = idx & 63;
        zi[r][k] = Z[(i0 + r) * DZc + k];
    }
    if (t < 16) { yis[t] = y[i0 + t]; azis[t] = g_az[i0 + t]; }
    __syncthreads();
    int half = t >> 7;
    int jl = t & 127;
    float acc = 0.0f;
    for (int j0 = 0; j0 < Bn; j0 += 128) {
        __syncthreads();
        for (int idx = t; idx < 128 * 64; idx += 256) {
            int r = idx >> 6, k = idx & 63;
            zj[r][k] = Z[(j0 + r) * DZc + k];
        }
        __syncthreads();
        int j = j0 + jl;
        float azj = g_az[j];
        float yj = y[j];
        #pragma unroll
        for (int ii = 0; ii < 8; ii++) {
            int il = half * 8 + ii;
            int i = i0 + il;
            if (i == j) continue;
            float d = 0.0f;
            #pragma unroll 16
            for (int k = 0; k < 64; k++) d += zi[il][k] * zj[jl][k];
            float raw = azis[il] + azj - 2.0f * d;
            float Cz = sz * fmaxf(raw, 0.0f);
            float zd = fmaxf(Cz, 1e-4f);
            float df = __logf(fabsf(yis[il] - yj) + 1e-6f) - __logf(zd + 1e-6f);
            acc += df * df;
        }
    }
    float bs = blockReduce256(acc, sh, t);
    if (t == 0) atomicAdd(&g_reg, (double)bs);
}

// ------------- loop kernels -------------
// Phase 1: Yp[by][i][c] = sum_{j in chunk} K0[i,j] * v_j * Zb[j,c]
__global__ void __launch_bounds__(256) k_p1() {
    __shared__ float Ks[16][68];
    __shared__ float Bs[16][CQ];
    __shared__ float vsh[256];
    int tx = threadIdx.x, ty = threadIdx.y;
    int t = ty * 16 + tx;
    int i0 = blockIdx.x * 64;
    int jbase = blockIdx.y * 256;
    vsh[t] = g_v[jbase + t];
    float acc[4][5];
    #pragma unroll
    for (int r = 0; r < 4; r++)
        #pragma unroll
        for (int q = 0; q < 5; q++) acc[r][q] = 0.0f;
    __syncthreads();
    for (int jc = 0; jc < 16; jc++) {
        #pragma unroll
        for (int e = 0; e < 4; e++) {
            int idx = t + e * 256;
            int r = idx >> 4, jj = idx & 15;
            Ks[jj][r] = g_K0[(size_t)(i0 + r) * Bn + jbase + jc * 16 + jj];
        }
        #pragma unroll
        for (int e = 0; e < 5; e++) {
            int idx = t + e * 256;
            int jj = idx / CQ, c = idx % CQ;
            Bs[jj][c] = vsh[jc * 16 + jj] * g_Zb[(jbase + jc * 16 + jj) * CQ + c];
        }
        __syncthreads();
        #pragma unroll
        for (int jj = 0; jj < 16; jj++) {
            float4 fa = *(const float4*)&Ks[jj][ty * 4];
            float a4[4] = {fa.x, fa.y, fa.z, fa.w};
            float fb[5];
            #pragma unroll
            for (int q = 0; q < 5; q++) fb[q] = Bs[jj][tx * 5 + q];
            #pragma unroll
            for (int r = 0; r < 4; r++)
                #pragma unroll
                for (int q = 0; q < 5; q++) acc[r][q] += a4[r] * fb[q];
        }
        __syncthreads();
    }
    #pragma unroll
    for (int r = 0; r < 4; r++)
        #pragma unroll
        for (int q = 0; q < 5; q++)
            g_Yp[((size_t)blockIdx.y * Bn + i0 + ty * 4 + r) * CQ + tx * 5 + q] = acc[r][q];
}

// Phase 1b: Y = u * sum of partials
__global__ void k_p1r() {
    int idx = blockIdx.x * 256 + threadIdx.x;
    if (idx >= Bn * CQ) return;
    int i = idx / CQ;
    float s = 0.0f;
    #pragma unroll
    for (int y = 0; y < NJ; y++) s += g_Yp[(size_t)y * Bn * CQ + idx];
    g_Y[idx] = g_u[i] * s;
}

// Phase 2: Pp[by][xc][c] = sum_{i in chunk} X[i,xc] * Y[i,c]; bx==0 also cs/asR partials
__global__ void __launch_bounds__(256) k_p2(const float* __restrict__ X) {
    __shared__ float Xs[16][17];
    __shared__ float Ms[16][CQ];
    __shared__ float axsh[16];
    int tx = threadIdx.x, ty = threadIdx.y;
    int t = ty * 16 + tx;
    int xc0 = blockIdx.x * 16;
    int ibase = blockIdx.y * 256;
    float acc[5] = {0.f, 0.f, 0.f, 0.f, 0.f};
    float csl = 0.0f, asl = 0.0f;
    bool docs = (blockIdx.x == 0) && (t < CQ);
    for (int ic = 0; ic < 16; ic++) {
        if (t < 16) axsh[t] = g_ax[ibase + ic * 16 + t];
        Xs[ty][tx] = X[(ibase + ic * 16 + ty) * DXc + xc0 + tx];
        #pragma unroll
        for (int e = 0; e < 5; e++) {
            int idx = t + e * 256;
            int ii = idx / CQ, c = idx % CQ;
            Ms[ii][c] = g_Y[(ibase + ic * 16 + ii) * CQ + c];
        }
        __syncthreads();
        #pragma unroll
        for (int ii = 0; ii < 16; ii++) {
            float fa = Xs[ii][tx];
            #pragma unroll
            for (int q = 0; q < 5; q++) acc[q] += fa * Ms[ii][ty * 5 + q];
        }
        if (docs) {
            #pragma unroll
            for (int ii = 0; ii < 16; ii++) {
                float m = Ms[ii][t];
                csl += m;
                asl += axsh[ii] * m;
            }
        }
        __syncthreads();
    }
    #pragma unroll
    for (int q = 0; q < 5; q++)
        g_Pp[((size_t)blockIdx.y * DXc + xc0 + tx) * CQ + ty * 5 + q] = acc[q];
    if (docs) { g_csp[blockIdx.y][t] = csl; g_asp[blockIdx.y][t] = asl; }
}

// Phase 2b: reduce P, cs, asR
__global__ void k_p2r() {
    int idx = blockIdx.x * 256 + threadIdx.x;
    float s = 0.0f;
    #pragma unroll
    for (int y = 0; y < NI; y++) s += g_Pp[(size_t)y * DXc * CQ + idx];
    g_P[idx] = s;
    if (blockIdx.x == 0 && threadIdx.x < CQ) {
        float cs = 0.0f, as = 0.0f;
        #pragma unroll
        for (int y = 0; y < NI; y++) { cs += g_csp[y][threadIdx.x]; as += g_asp[y][threadIdx.x]; }
        g_cs[threadIdx.x] = cs;
        g_asR[threadIdx.x] = as;
    }
}

// Phase 3: A[i,c] = sx*(ax_i*cs_c + asR_c) - 2*sx*sum_k X[i,k]*P[k,c]
__global__ void __launch_bounds__(256) k_p3(const float* __restrict__ X) {
    __shared__ float Xt[16][68];
    __shared__ float Ps[16][16];
    int tx = threadIdx.x, ty = threadIdx.y;
    int t = ty * 16 + tx;
    int i0 = blockIdx.x * 64, c0 = blockIdx.y * 16;
    float acc[4] = {0.f, 0.f, 0.f, 0.f};
    for (int k0 = 0; k0 < DXc; k0 += 16) {
        #pragma unroll
        for (int e = 0; e < 4; e++) {
            int idx = t + e * 256;
            int r = idx >> 4, kk = idx & 15;
            Xt[kk][r] = X[(i0 + r) * DXc + k0 + kk];
        }
        Ps[t >> 4][t & 15] = g_P[(k0 + (t >> 4)) * CQ + c0 + (t & 15)];
        __syncthreads();
        #pragma unroll
        for (int kk = 0; kk < 16; kk++) {
            float4 fa = *(const float4*)&Xt[kk][ty * 4];
            float a4[4] = {fa.x, fa.y, fa.z, fa.w};
            float b = Ps[kk][tx];
            #pragma unroll
            for (int r = 0; r < 4; r++) acc[r] += a4[r] * b;
        }
        __syncthreads();
    }
    float sxv = g_sx;
    int c = c0 + tx;
    float csc = g_cs[c], asc = g_asR[c];
    #pragma unroll
    for (int r = 0; r < 4; r++) {
        int i = i0 + ty * 4 + r;
        g_A[i * CQ + c] = sxv * (g_ax[i] * csc + asc) - 2.0f * sxv * acc[r];
    }
}

// Phase 4: K0' = exp(2sz*az_j*a0_i + 2sz*a1_i - 4sz*(A_i . Z_j) - cx_i - cz_j)
__global__ void __launch_bounds__(256) k_p4() {
    __shared__ float At[64][68];
    __shared__ float Zt[64][68];
    __shared__ float a0s[64], a1s[64], cxs[64], azs[64], czs[64];
    int tx = threadIdx.x, ty = threadIdx.y;
    int t = ty * 16 + tx;
    int i0 = blockIdx.y * 64, j0 = blockIdx.x * 64;
    #pragma unroll
    for (int e = 0; e < 16; e++) {
        int idx = t + e * 256;
        int r = idx >> 6, k = idx & 63;
        At[k][r] = g_A[(i0 + r) * CQ + k];
        Zt[k][r] = g_Zb[(j0 + r) * CQ + k];
    }
    if (t < 64) {
        a0s[t] = g_A[(i0 + t) * CQ + 64];
        a1s[t] = g_A[(i0 + t) * CQ + 65];
        cxs[t] = g_cx[i0 + t];
        azs[t] = g_az[j0 + t];
        czs[t] = g_cz[j0 + t];
    }
    __syncthreads();
    float acc[4][4];
    #pragma unroll
    for (int r = 0; r < 4; r++)
        #pragma unroll
        for (int c = 0; c < 4; c++) acc[r][c] = 0.0f;
    #pragma unroll
    for (int k = 0; k < 64; k++) {
        float4 fa = *(const float4*)&At[k][ty * 4];
        float4 fb = *(const float4*)&Zt[k][tx * 4];
        float a4[4] = {fa.x, fa.y, fa.z, fa.w};
        float b4[4] = {fb.x, fb.y, fb.z, fb.w};
        #pragma unroll
        for (int r = 0; r < 4; r++)
            #pragma unroll
            for (int c = 0; c < 4; c++) acc[r][c] += a4[r] * b4[c];
    }
    float sz = g_sz;
    float al[4], be[4], azc[4], czc[4];
    #pragma unroll
    for (int r = 0; r < 4; r++) {
        al[r] = 2.0f * sz * a0s[ty * 4 + r];
        be[r] = 2.0f * sz * a1s[ty * 4 + r] - cxs[ty * 4 + r];
    }
    #pragma unroll
    for (int c = 0; c < 4; c++) { azc[c] = azs[tx * 4 + c]; czc[c] = czs[tx * 4 + c]; }
    float val[4][4];
    #pragma unroll
    for (int r = 0; r < 4; r++)
        #pragma unroll
        for (int c = 0; c < 4; c++)
            val[r][c] = __expf(al[r] * azc[c] + be[r] - czc[c] - 4.0f * sz * acc[r][c]);
    #pragma unroll
    for (int r = 0; r < 4; r++) {
        float4 w = make_float4(val[r][0], val[r][1], val[r][2], val[r][3]);
        *(float4*)&g_K0[(size_t)(i0 + ty * 4 + r) * Bn + j0 + tx * 4] = w;
    }
    #pragma unroll
    for (int c = 0; c < 4; c++) {
        float4 w = make_float4(val[0][c], val[1][c], val[2][c], val[3][c]);
        *(float4*)&g_K0T[(size_t)(j0 + tx * 4 + c) * Bn + i0 + ty * 4] = w;
    }
}

// fused 5-round normalization, 2 rows per block iteration
__global__ void __launch_bounds__(256) k_norm() {
    __shared__ float vs[Bn];
    __shared__ float sh2[2][4];
    int tid = threadIdx.x;
    int half = tid >> 7;
    int lt = tid & 127;
    int sense = *((volatile int*)&g_barSense);
    {
        int gt = blockIdx.x * 256 + tid;
        if (gt < Bn) { g_u[gt] = 1.0f; g_v[gt] = 1.0f; }
    }
    #define GRID_BAR() do {                                          \
        __syncthreads();                                             \
        __threadfence();                                             \
        if (tid == 0) {                                              \
            int tgt = sense ^ 1;                                     \
            if (atomicAdd(&g_barCount, 1) == NBLK - 1) {             \
                g_barCount = 0;                                      \
                __threadfence();                                     \
                *((volatile int*)&g_barSense) = tgt;                 \
            } else {                                                 \
                while (*((volatile int*)&g_barSense) != tgt) { __nanosleep(32); } \
            }                                                        \
        }                                                            \
        sense ^= 1;                                                  \
        __syncthreads();                                             \
        __threadfence();                                             \
    } while (0)
    GRID_BAR();
    for (int round = 0; round < 5; round++) {
        // row pass
        for (int j = tid; j < Bn; j += 256) vs[j] = g_v[j];
        __syncthreads();
        for (int ii = blockIdx.x; ii < Bn / 2; ii += NBLK) {
            int i = ii * 2 + half;
            const float4* row4 = (const float4*)&g_K0[(size_t)i * Bn];
            const float4* vs4 = (const float4*)vs;
            float s = 0.0f;
            #pragma unroll
            for (int e = 0; e < 4; e++) {
                int j4 = lt + e * 128;
                float4 kv = row4[j4];
                float4 vv = vs4[j4];
                s += kv.x * vv.x + kv.y * vv.y + kv.z * vv.z + kv.w * vv.w;
            }
            #pragma unroll
            for (int o = 16; o; o >>= 1) s += __shfl_down_sync(0xffffffffu, s, o);
            if ((lt & 31) == 0) sh2[half][lt >> 5] = s;
            __syncthreads();
            if (lt == 0) {
                float tot = sh2[half][0] + sh2[half][1] + sh2[half][2] + sh2[half][3];
                float uo = g_u[i];
                g_u[i] = uo * INV_B / (uo * tot + 1e-8f);
            }
            __syncthreads();
        }
        GRID_BAR();
        // col pass
        for (int j = tid; j < Bn; j += 256) vs[j] = g_u[j];
        __syncthreads();
        for (int ii = blockIdx.x; ii < Bn / 2; ii += NBLK) {
            int j = ii * 2 + half;
            const float4* col4 = (const float4*)&g_K0T[(size_t)j * Bn];
            const float4* us4 = (const float4*)vs;
            float s = 0.0f;
            #pragma unroll
            for (int e = 0; e < 4; e++) {
                int j4 = lt + e * 128;
                float4 kv = col4[j4];
                float4 vv = us4[j4];
                s += kv.x * vv.x + kv.y * vv.y + kv.z * vv.z + kv.w * vv.w;
            }
            #pragma unroll
            for (int o = 16; o; o >>= 1) s += __shfl_down_sync(0xffffffffu, s, o);
            if ((lt & 31) == 0) sh2[half][lt >> 5] = s;
            __syncthreads();
            if (lt == 0) {
                float tot = sh2[half][0] + sh2[half][1] + sh2[half][2] + sh2[half][3];
                float vo = g_v[j];
                g_v[j] = vo * INV_B / (vo * tot + 1e-8f);
            }
            __syncthreads();
        }
        if (round < 4) GRID_BAR();
    }
    #undef GRID_BAR
}

// epilogue: cross_term = sum_ij u_i K0_ij v_j * sz*(az_j*a0_i + a1_i - 2*A_i.Z_j)
__global__ void __launch_bounds__(256) k_cross() {
    __shared__ float At[64][68];
    __shared__ float Zt[64][68];
    __shared__ float a0s[64], a1s[64], azs[64], us[64];
    __shared__ float sh[8];
    int tx = threadIdx.x, ty = threadIdx.y;
    int t = ty * 16 + tx;
    int i0 = blockIdx.y * 64, j0 = blockIdx.x * 64;
    #pragma unroll
    for (int e = 0; e < 16; e++) {
        int idx = t + e * 256;
        int r = idx >> 6, k = idx & 63;
        At[k][r] = g_A[(i0 + r) * CQ + k];
        Zt[k][r] = g_Zb[(j0 + r) * CQ + k];
    }
    if (t < 64) {
        a0s[t] = g_A[(i0 + t) * CQ + 64];
        a1s[t] = g_A[(i0 + t) * CQ + 65];
        azs[t] = g_az[j0 + t];
        us[t]  = g_u[i0 + t];
    }
    __syncthreads();
    float acc[4][4];
    #pragma unroll
    for (int r = 0; r < 4; r++)
        #pragma unroll
        for (int c = 0; c < 4; c++) acc[r][c] = 0.0f;
    #pragma unroll
    for (int k = 0; k < 64; k++) {
        float4 fa = *(const float4*)&At[k][ty * 4];
        float4 fb = *(const float4*)&Zt[k][tx * 4];
        float a4[4] = {fa.x, fa.y, fa.z, fa.w};
        float b4[4] = {fb.x, fb.y, fb.z, fb.w};
        #pragma unroll
        for (int r = 0; r < 4; r++)
            #pragma unroll
            for (int c = 0; c < 4; c++) acc[r][c] += a4[r] * b4[c];
    }
    float sz = g_sz;
    float4 vj = *(const float4*)&g_v[j0 + tx * 4];
    float v4[4] = {vj.x, vj.y, vj.z, vj.w};
    float part = 0.0f;
    #pragma unroll
    for (int r = 0; r < 4; r++) {
        int i = i0 + ty * 4 + r;
        float ui = us[ty * 4 + r];
        float a0 = a0s[ty * 4 + r], a1 = a1s[ty * 4 + r];
        float4 k4 = *(const float4*)&g_K0[(size_t)i * Bn + j0 + tx * 4];
        float kk[4] = {k4.x, k4.y, k4.z, k4.w};
        #pragma unroll
        for (int c = 0; c < 4; c++) {
            float crossv = sz * (azs[tx * 4 + c] * a0 + a1 - 2.0f * acc[r][c]);
            part += crossv * ui * kk[c] * v4[c];
        }
    }
    float bs = blockReduce256(part, sh, t);
    if (t == 0) atomicAdd(&g_cross, (double)bs);
}

__global__ void k_final(float* out) {
    float gw = g_mCx2 + g_mCz2 - 2.0f * (float)g_cross;
    gw = fmaxf(gw, 0.0f);
    double denom = (double)Bn * (double)(Bn - 1);
    out[0] = gw + (float)(g_reg / denom);
}

// ------------- launch -------------
extern "C" void kernel_launch(void* const* d_in, const int* in_sizes, int n_in,
                              void* d_out, int out_size) {
    const float* x = (const float*)d_in[0];
    const float* z = (const float*)d_in[1];
    const float* y = (const float*)d_in[2];
    float* out = (float*)d_out;
    (void)in_sizes; (void)n_in; (void)out_size;

    dim3 t16(16, 16);
    dim3 g3232(32, 32);
    dim3 gp1(32, NJ);
    dim3 gp2(16, NI);
    dim3 gp3(32, 5);

    k_init<<<8, 256>>>();
    k_sqnorm<<<Bn, 256>>>(x, DXc, 0);
    k_sqnorm<<<Bn, 256>>>(z, DZc, 1);
    k_stats<<<g3232, t16>>>(x, DXc, 0);
    k_stats<<<g3232, t16>>>(z, DZc, 1);
    k_scalars<<<1, 256>>>();
    k_zb<<<(Bn * CQ + 255) / 256, 256>>>(z);
    k_colsums<<<8, 256>>>(x, z);
    k_reg<<<Bn / 16, 256>>>(z, y);
    k_pq2<<<Bn / 8, 256>>>(x, z);

    // iteration 1 (rank-1 exponent, stabilized)
    k_m1<<<8, 256>>>();
    k_K1<<<g3232, t16>>>();
    k_norm<<<NBLK, 256>>>();

    // iterations 2..50
    for (int it = 1; it < 50; it++) {
        k_p1<<<gp1, t16>>>();
        k_p1r<<<(Bn * CQ + 255) / 256, 256>>>();
        k_p2<<<gp2, t16>>>(x);
        k_p2r<<<DXc * CQ / 256, 256>>>();
        k_p3<<<gp3, t16>>>(x);
        k_p4<<<g3232, t16>>>();
        k_norm<<<NBLK, 256>>>();
    }
    // epilogue: cross term with final T
    k_p1<<<gp1, t16>>>();
    k_p1r<<<(Bn * CQ + 255) / 256, 256>>>();
    k_p2<<<gp2, t16>>>(x);
    k_p2r<<<DXc * CQ / 256, 256>>>();
    k_p3<<<gp3, t16>>>(x);
    k_cross<<<g3232, t16>>>();
    k_final<<<1, 1>>>(out);
}